// round 13
// baseline (speedup 1.0000x reference)
#include <cuda_runtime.h>
#include <cuda_bf16.h>

#define NROWS    8192
#define NF       1024
#define NTHREADS 256
#define NBLOCKS  1024
#define RPB      (NROWS / NBLOCKS)   // 8 rows per block in phase 2
#define NPAIR    (RPB / 2)           // 4 row-pairs per block

__device__ float2 g_stats[NROWS];    // {mu, rstd} per row

// ---------------- Phase 1: one warp per row -> row stats ----------------
__global__ __launch_bounds__(NTHREADS)
void kan_stats(const float* __restrict__ x)
{
    const int wid  = threadIdx.x >> 5;
    const int lane = threadIdx.x & 31;
    const int row  = blockIdx.x * 8 + wid;

    const float4* xr = reinterpret_cast<const float4*>(x + (size_t)row * NF);

    float sum = 0.0f, sq = 0.0f;
    #pragma unroll
    for (int k = 0; k < 8; k++) {
        const float4 t = xr[k * 32 + lane];
        sum += (t.x + t.y) + (t.z + t.w);
        sq   = fmaf(t.x, t.x, fmaf(t.y, t.y, fmaf(t.z, t.z, fmaf(t.w, t.w, sq))));
    }

    #pragma unroll
    for (int off = 16; off; off >>= 1) {
        sum += __shfl_xor_sync(0xffffffffu, sum, off);
        sq  += __shfl_xor_sync(0xffffffffu, sq,  off);
    }

    if (lane == 0) {
        const float mu = sum * (1.0f / NF);
        g_stats[row] = make_float2(mu,
            rsqrtf(sq * (1.0f / NF) - mu * mu + 1e-5f));
    }
}

// ---------------- Phase 2: pure elementwise map, 2 rows in flight ----------------
__global__ __launch_bounds__(NTHREADS)
void kan_map(const float* __restrict__ x,
             const float* __restrict__ lnw,
             const float* __restrict__ lnb,
             const float* __restrict__ sw,
             const float* __restrict__ bw,
             const float* __restrict__ grid,
             float* __restrict__ out)
{
    // Swizzled transposed planes: coeff i of feature f at i*1024 + (f&3)*256 + (f>>2).
    // Thread tid owns features 4*tid+c -> tap addr = i*1024 + c*256 + tid,
    // bank = tid mod 32 = lane: conflict-free under divergent plane index.
    __shared__ float s_swT[8 * NF];

    const int tid = threadIdx.x;

    for (int f = tid; f < NF; f += NTHREADS) {
        float4 a = *reinterpret_cast<const float4*>(sw + f * 8);
        float4 b = *reinterpret_cast<const float4*>(sw + f * 8 + 4);
        const int base = ((f & 3) << 8) + (f >> 2);
        s_swT[0 * NF + base] = a.x * (1.0f/6.0f);
        s_swT[1 * NF + base] = a.y * (1.0f/6.0f);
        s_swT[2 * NF + base] = a.z * (1.0f/6.0f);
        s_swT[3 * NF + base] = a.w * (1.0f/6.0f);
        s_swT[4 * NF + base] = b.x * (1.0f/6.0f);
        s_swT[5 * NF + base] = b.y * (1.0f/6.0f);
        s_swT[6 * NF + base] = b.z * (1.0f/6.0f);
        s_swT[7 * NF + base] = b.w * (1.0f/6.0f);
    }

    const float g0    = grid[0];
    const float g11   = grid[11];
    const float inv_h = 11.0f / (g11 - g0);
    const float h     = (g11 - g0) * (1.0f / 11.0f);

    const float4 w4 = *reinterpret_cast<const float4*>(lnw + 4 * tid);
    const float4 b4 = *reinterpret_cast<const float4*>(lnb + 4 * tid);
    const float4 s4 = *reinterpret_cast<const float4*>(bw  + 4 * tid);
    float A[4], G[4], W[4];
    A[0] = w4.x * inv_h; A[1] = w4.y * inv_h; A[2] = w4.z * inv_h; A[3] = w4.w * inv_h;
    G[0] = (b4.x - g0) * inv_h; G[1] = (b4.y - g0) * inv_h;
    G[2] = (b4.z - g0) * inv_h; G[3] = (b4.w - g0) * inv_h;
    W[0] = s4.x; W[1] = s4.y; W[2] = s4.z; W[3] = s4.w;

    __syncthreads();   // only barrier: after table staging

    const size_t col = 4 * tid;
    const float* xc  = x + col;
    float*       oc  = out + col;

    // Pipeline: 2 rows in flight per iteration
    float4 curA = *reinterpret_cast<const float4*>(xc + (size_t)blockIdx.x * NF);
    float4 curB = *reinterpret_cast<const float4*>(xc + (size_t)(blockIdx.x + NBLOCKS) * NF);
    float2 stA  = g_stats[blockIdx.x];
    float2 stB  = g_stats[blockIdx.x + NBLOCKS];

    #pragma unroll
    for (int k = 0; k < NPAIR; k++) {
        const int rowA = blockIdx.x + (2 * k) * NBLOCKS;
        const int rowB = rowA + NBLOCKS;

        // Prefetch next pair while this pair computes
        float4 nxtA, nxtB;
        float2 snA, snB;
        if (k + 1 < NPAIR) {
            nxtA = *reinterpret_cast<const float4*>(xc + (size_t)(rowA + 2 * NBLOCKS) * NF);
            nxtB = *reinterpret_cast<const float4*>(xc + (size_t)(rowB + 2 * NBLOCKS) * NF);
            snA  = g_stats[rowA + 2 * NBLOCKS];
            snB  = g_stats[rowB + 2 * NBLOCKS];
        }

        const float vA[4] = {curA.x, curA.y, curA.z, curA.w};
        const float vB[4] = {curB.x, curB.y, curB.z, curB.w};

        float4 resA, resB;
        float* rpA = &resA.x;
        float* rpB = &resB.x;

        // 8 independent chains: 2 rows x 4 features, interleaved by the compiler
        #pragma unroll
        for (int c = 0; c < 4; c++) {
            #pragma unroll
            for (int r = 0; r < 2; r++) {
                const float v    = r ? vB[c] : vA[c];
                const float mu   = r ? stB.x : stA.x;
                const float rstd = r ? stB.y : stA.y;

                const float xn = fmaf((v - mu) * rstd, A[c], G[c]); // knot units
                const float n  = fmaf(xn, h, g0);                   // normed

                const float fj = floorf(xn);
                const int   j  = (int)fj;
                const float t  = xn - fj;
                const float u  = 1.0f - t;
                const float t2 = t * t;
                const float u2 = u * u;
                const float B0 = u2 * u;
                const float B3 = t2 * t;
                const float B1 = fmaf(fmaf(3.0f, t, -6.0f), t2, 4.0f);
                const float B2 = fmaf(fmaf(3.0f, u, -6.0f), u2, 4.0f);

                const float* p = s_swT + (c << 8) + tid + ((j - 3) << 10);
                const int i0 = j - 3;
                float s = 0.0f;
                if ((unsigned)(i0    ) < 8u) s = fmaf(B0, p[0 * NF], s);
                if ((unsigned)(i0 + 1) < 8u) s = fmaf(B1, p[1 * NF], s);
                if ((unsigned)(i0 + 2) < 8u) s = fmaf(B2, p[2 * NF], s);
                if ((unsigned)(i0 + 3) < 8u) s = fmaf(B3, p[3 * NF], s);

                // silu(n) = m + m*tanh(m), m = n/2  (MUFU tanh)
                const float m = 0.5f * n;
                float th;
                asm("tanh.approx.f32 %0, %1;" : "=f"(th) : "f"(m));
                const float sil = fmaf(m, th, m);

                if (r) rpB[c] = fmaf(W[c], sil, s);
                else   rpA[c] = fmaf(W[c], sil, s);
            }
        }

        *reinterpret_cast<float4*>(oc + (size_t)rowA * NF) = resA;
        *reinterpret_cast<float4*>(oc + (size_t)rowB * NF) = resB;

        curA = nxtA; curB = nxtB;
        stA  = snA;  stB  = snB;
    }
}

extern "C" void kernel_launch(void* const* d_in, const int* in_sizes, int n_in,
                              void* d_out, int out_size)
{
    const float* x    = (const float*)d_in[0];
    const float* lnw  = (const float*)d_in[1];
    const float* lnb  = (const float*)d_in[2];
    const float* sw   = (const float*)d_in[3];
    const float* bw   = (const float*)d_in[4];
    const float* grid = (const float*)d_in[5];
    float* out = (float*)d_out;

    kan_stats<<<NROWS / 8, NTHREADS>>>(x);
    kan_map<<<NBLOCKS, NTHREADS>>>(x, lnw, lnb, sw, bw, grid, out);
}

// round 14
// speedup vs baseline: 1.0115x; 1.0115x over previous
#include <cuda_runtime.h>
#include <cuda_bf16.h>

#define NROWS    8192
#define NF       1024
#define NJ       11                  // knot intervals j = 0..10
#define POLY_N   (NJ * NF)           // 11264 float4 entries
#define SMEM_BYTES (POLY_N * 16)     // 176 KB

__device__ float2 g_stats[NROWS];    // {mu, rstd} per row
__device__ float4 g_poly[POLY_N];    // per-(j, f) cubic coeffs {c0,c1,c2,c3}

// ---- Phase 1: row stats (all blocks) + poly table build (blocks 0..43) ----
__global__ __launch_bounds__(256)
void kan_stats(const float* __restrict__ x, const float* __restrict__ sw)
{
    const int tid  = threadIdx.x;
    const int wid  = tid >> 5;
    const int lane = tid & 31;
    const int row  = blockIdx.x * 8 + wid;

    const float4* xr = reinterpret_cast<const float4*>(x + (size_t)row * NF);

    float sum = 0.0f, sq = 0.0f;
    #pragma unroll
    for (int k = 0; k < 8; k++) {
        const float4 t = xr[k * 32 + lane];
        sum += (t.x + t.y) + (t.z + t.w);
        sq   = fmaf(t.x, t.x, fmaf(t.y, t.y, fmaf(t.z, t.z, fmaf(t.w, t.w, sq))));
    }
    #pragma unroll
    for (int off = 16; off; off >>= 1) {
        sum += __shfl_xor_sync(0xffffffffu, sum, off);
        sq  += __shfl_xor_sync(0xffffffffu, sq,  off);
    }
    if (lane == 0) {
        const float mu = sum * (1.0f / NF);
        g_stats[row] = make_float2(mu,
            rsqrtf(sq * (1.0f / NF) - mu * mu + 1e-5f));
    }

    // Poly build: entry e = j*NF + f.  S|interval j (local t) =
    //   (1/6)[w0(1-t)^3 + w1(3t^3-6t^2+4) + w2(-3t^3+3t^2+3t+1) + w3 t^3],
    //   wk = sw[f*8 + j-3+k] (0 outside 0..7 -> truncation baked in).
    const int e = blockIdx.x * 256 + tid;
    if (e < POLY_N) {
        const int j = e >> 10;        // 0..10
        const int f = e & (NF - 1);
        const int i0 = j - 3;
        float w[4];
        #pragma unroll
        for (int k = 0; k < 4; k++) {
            const int idx = i0 + k;
            w[k] = ((unsigned)idx < 8u) ? sw[f * 8 + idx] : 0.0f;
        }
        float4 c;
        c.x = (w[0] + 4.0f * w[1] + w[2]) * (1.0f / 6.0f);
        c.y = (w[2] - w[0]) * 0.5f;
        c.z = (w[0] - 2.0f * w[1] + w[2]) * 0.5f;
        c.w = (w[3] - w[0]) * (1.0f / 6.0f) + (w[1] - w[2]) * 0.5f;
        g_poly[e] = c;
    }
}

// ---- Phase 2: elementwise map; 1 feature/thread, poly table in smem ----
__global__ __launch_bounds__(1024)
void kan_map(const float* __restrict__ x,
             const float* __restrict__ lnw,
             const float* __restrict__ lnb,
             const float* __restrict__ bw,
             const float* __restrict__ grid,
             float* __restrict__ out,
             int nblocks)
{
    extern __shared__ float4 s_poly[];   // 11264 entries, 176 KB

    const int tid = threadIdx.x;         // == feature index

    // Stage poly table: entry j*NF+tid -> lanes contiguous 16B stride;
    // j offset = 16384 B = 0 mod 32 banks -> conflict-free LDS.128 under
    // divergent j.
    #pragma unroll
    for (int i = 0; i < NJ; i++)
        s_poly[i * NF + tid] = g_poly[i * NF + tid];

    const float g0    = grid[0];
    const float g11   = grid[11];
    const float inv_h = 11.0f / (g11 - g0);
    const float h     = (g11 - g0) * (1.0f / 11.0f);

    const float A = lnw[tid] * inv_h;          // LN slope in knot units
    const float G = (lnb[tid] - g0) * inv_h;   // LN offset in knot units
    const float W = bw[tid];

    __syncthreads();

    float  v  = x[(size_t)blockIdx.x * NF + tid];
    float2 st = g_stats[blockIdx.x];

    for (int row = blockIdx.x; row < NROWS; row += nblocks) {
        // Prefetch next grid-stride row
        float  vn;
        float2 stn;
        const int nrow = row + nblocks;
        if (nrow < NROWS) {
            vn  = x[(size_t)nrow * NF + tid];
            stn = g_stats[nrow];
        }

        const float k1 = st.y * A;                 // rstd * A
        const float k2 = fmaf(-st.x, k1, G);       // G - mu*rstd*A
        const float xn = fmaf(v, k1, k2);          // knot units
        const float n  = fmaf(xn, h, g0);          // normed value

        const float fj = floorf(xn);
        const int   j  = (int)fj;
        const float t  = xn - fj;
        const int   jc = min(max(j, 0), NJ - 1);

        const float4 c = s_poly[jc * NF + tid];    // one LDS.128
        float s = fmaf(fmaf(fmaf(c.w, t, c.z), t, c.y), t, c.x);
        if ((unsigned)j > 10u) s = 0.0f;           // outside knot span

        // silu(n) = m + m*tanh(m), m = n/2  (MUFU tanh)
        const float m = 0.5f * n;
        float th;
        asm("tanh.approx.f32 %0, %1;" : "=f"(th) : "f"(m));
        const float sil = fmaf(m, th, m);

        out[(size_t)row * NF + tid] = fmaf(W, sil, s);

        v  = vn;
        st = stn;
    }
}

extern "C" void kernel_launch(void* const* d_in, const int* in_sizes, int n_in,
                              void* d_out, int out_size)
{
    const float* x    = (const float*)d_in[0];
    const float* lnw  = (const float*)d_in[1];
    const float* lnb  = (const float*)d_in[2];
    const float* sw   = (const float*)d_in[3];
    const float* bw   = (const float*)d_in[4];
    const float* grid = (const float*)d_in[5];
    float* out = (float*)d_out;

    // Host-side, non-stream calls: run only during capture, free at replay.
    int dev = 0, nsm = 148;
    cudaGetDevice(&dev);
    cudaDeviceGetAttribute(&nsm, cudaDevAttrMultiProcessorCount, dev);
    cudaFuncSetAttribute(kan_map,
                         cudaFuncAttributeMaxDynamicSharedMemorySize,
                         SMEM_BYTES);

    kan_stats<<<NROWS / 8, 256>>>(x, sw);
    kan_map<<<nsm, 1024, SMEM_BYTES>>>(x, lnw, lnb, bw, grid, out, nsm);
}

// round 15
// speedup vs baseline: 1.1015x; 1.0890x over previous
#include <cuda_runtime.h>
#include <cuda_bf16.h>

#define NROWS    8192
#define NF       1024
#define NJ       11                  // knot intervals j = 0..10
#define POLY_N   (NJ * NF)           // 11264 float4 entries
#define SMEM_BYTES (POLY_N * 16)     // 176 KB

__device__ float2 g_stats[NROWS];    // {mu, rstd} per row
__device__ float4 g_poly[POLY_N];    // per-(j, f) cubic coeffs {c0,c1,c2,c3}

// ---- Phase 1: row stats (all blocks) + poly table build (blocks 0..43) ----
__global__ __launch_bounds__(256)
void kan_stats(const float* __restrict__ x, const float* __restrict__ sw)
{
    const int tid  = threadIdx.x;
    const int wid  = tid >> 5;
    const int lane = tid & 31;
    const int row  = blockIdx.x * 8 + wid;

    const float4* xr = reinterpret_cast<const float4*>(x + (size_t)row * NF);

    float sum = 0.0f, sq = 0.0f;
    #pragma unroll
    for (int k = 0; k < 8; k++) {
        const float4 t = xr[k * 32 + lane];
        sum += (t.x + t.y) + (t.z + t.w);
        sq   = fmaf(t.x, t.x, fmaf(t.y, t.y, fmaf(t.z, t.z, fmaf(t.w, t.w, sq))));
    }
    #pragma unroll
    for (int off = 16; off; off >>= 1) {
        sum += __shfl_xor_sync(0xffffffffu, sum, off);
        sq  += __shfl_xor_sync(0xffffffffu, sq,  off);
    }
    if (lane == 0) {
        const float mu = sum * (1.0f / NF);
        g_stats[row] = make_float2(mu,
            rsqrtf(sq * (1.0f / NF) - mu * mu + 1e-5f));
    }

    // Poly build: entry e = j*NF + f (truncation baked in: wk=0 outside 0..7)
    const int e = blockIdx.x * 256 + tid;
    if (e < POLY_N) {
        const int j = e >> 10;        // 0..10
        const int f = e & (NF - 1);
        const int i0 = j - 3;
        float w[4];
        #pragma unroll
        for (int k = 0; k < 4; k++) {
            const int idx = i0 + k;
            w[k] = ((unsigned)idx < 8u) ? sw[f * 8 + idx] : 0.0f;
        }
        float4 c;
        c.x = (w[0] + 4.0f * w[1] + w[2]) * (1.0f / 6.0f);
        c.y = (w[2] - w[0]) * 0.5f;
        c.z = (w[0] - 2.0f * w[1] + w[2]) * 0.5f;
        c.w = (w[3] - w[0]) * (1.0f / 6.0f) + (w[1] - w[2]) * 0.5f;
        g_poly[e] = c;
    }
}

// ---- Phase 2: elementwise map; 1 feature/thread, 4 rows in flight ----
__global__ __launch_bounds__(1024)
void kan_map(const float* __restrict__ x,
             const float* __restrict__ lnw,
             const float* __restrict__ lnb,
             const float* __restrict__ bw,
             const float* __restrict__ grid,
             float* __restrict__ out,
             int nblocks)
{
    extern __shared__ float4 s_poly[];   // 11264 entries, 176 KB

    const int tid = threadIdx.x;         // == feature index

    // Stage poly table: j offset = 16 KB = 0 mod 32 banks -> conflict-free
    // LDS.128 under divergent j.
    #pragma unroll
    for (int i = 0; i < NJ; i++)
        s_poly[i * NF + tid] = g_poly[i * NF + tid];

    const float g0    = grid[0];
    const float g11   = grid[11];
    const float inv_h = 11.0f / (g11 - g0);
    const float h     = (g11 - g0) * (1.0f / 11.0f);

    const float A = lnw[tid] * inv_h;          // LN slope in knot units
    const float G = (lnb[tid] - g0) * inv_h;   // LN offset in knot units
    const float W = bw[tid];

    __syncthreads();

    const int step = 4 * nblocks;

    for (int row0 = blockIdx.x; row0 < NROWS; row0 += step) {
        // Batch-load 4 rows: 8 independent LDGs in flight
        float  v[4];
        float2 st[4];
        #pragma unroll
        for (int r = 0; r < 4; r++) {
            const int rr = row0 + r * nblocks;
            if (rr < NROWS) {
                v[r]  = x[(size_t)rr * NF + tid];
                st[r] = g_stats[rr];
            }
        }

        // 4 independent compute chains
        float res[4];
        #pragma unroll
        for (int r = 0; r < 4; r++) {
            const float k1 = st[r].y * A;              // rstd * A
            const float k2 = fmaf(-st[r].x, k1, G);    // G - mu*rstd*A
            const float xn = fmaf(v[r], k1, k2);       // knot units
            const float n  = fmaf(xn, h, g0);          // normed value

            const float fj = floorf(xn);
            const int   j  = (int)fj;
            const float t  = xn - fj;
            const int   jc = min(max(j, 0), NJ - 1);

            const float4 c = s_poly[jc * NF + tid];    // one LDS.128
            float s = fmaf(fmaf(fmaf(c.w, t, c.z), t, c.y), t, c.x);
            if ((unsigned)j > 10u) s = 0.0f;           // outside knot span

            // silu(n) = m + m*tanh(m), m = n/2  (MUFU tanh)
            const float m = 0.5f * n;
            float th;
            asm("tanh.approx.f32 %0, %1;" : "=f"(th) : "f"(m));
            res[r] = fmaf(W, fmaf(m, th, m), s);
        }

        // 4 stores
        #pragma unroll
        for (int r = 0; r < 4; r++) {
            const int rr = row0 + r * nblocks;
            if (rr < NROWS)
                out[(size_t)rr * NF + tid] = res[r];
        }
    }
}

extern "C" void kernel_launch(void* const* d_in, const int* in_sizes, int n_in,
                              void* d_out, int out_size)
{
    const float* x    = (const float*)d_in[0];
    const float* lnw  = (const float*)d_in[1];
    const float* lnb  = (const float*)d_in[2];
    const float* sw   = (const float*)d_in[3];
    const float* bw   = (const float*)d_in[4];
    const float* grid = (const float*)d_in[5];
    float* out = (float*)d_out;

    // Host-side, non-stream calls: run during capture, free at replay.
    int dev = 0, nsm = 148;
    cudaGetDevice(&dev);
    cudaDeviceGetAttribute(&nsm, cudaDevAttrMultiProcessorCount, dev);
    cudaFuncSetAttribute(kan_map,
                         cudaFuncAttributeMaxDynamicSharedMemorySize,
                         SMEM_BYTES);

    kan_stats<<<NROWS / 8, 256>>>(x, sw);
    kan_map<<<nsm, 1024, SMEM_BYTES>>>(x, lnw, lnb, bw, grid, out, nsm);
}